// round 4
// baseline (speedup 1.0000x reference)
#include <cuda_runtime.h>
#include <cuda_fp16.h>

#define H 8192
#define T 64

// Scratch (device globals: the sanctioned allocation-free workaround).
// fp16 copy of W_hh: 128 MiB.
__device__ __half g_whh[(size_t)H * (size_t)H];
// Two K-split halves of the pre-activations pre[t][j] = x_t . W_ih^T  (no b yet).
__device__ float g_pre0[T * H];
__device__ float g_pre1[T * H];

// ---------------------------------------------------------------------------
// K1: convert W_hh fp32 -> fp16 (384 MB traffic, ~50 us)
// One thread per 8 elements; grid covers H*H exactly.
// ---------------------------------------------------------------------------
__global__ void __launch_bounds__(256) k_convert(const float* __restrict__ whh) {
    size_t i = ((size_t)blockIdx.x * 256u + threadIdx.x) * 8u;
    float4 a = *reinterpret_cast<const float4*>(whh + i);
    float4 c = *reinterpret_cast<const float4*>(whh + i + 4);
    __half2 h0 = __floats2half2_rn(a.x, a.y);
    __half2 h1 = __floats2half2_rn(a.z, a.w);
    __half2 h2 = __floats2half2_rn(c.x, c.y);
    __half2 h3 = __floats2half2_rn(c.z, c.w);
    uint4 o;
    o.x = reinterpret_cast<unsigned int&>(h0);
    o.y = reinterpret_cast<unsigned int&>(h1);
    o.z = reinterpret_cast<unsigned int&>(h2);
    o.w = reinterpret_cast<unsigned int&>(h3);
    *reinterpret_cast<uint4*>(g_whh + i) = o;
}

// ---------------------------------------------------------------------------
// K2: phase-1 SGEMM  pre[t][j] = sum_k x[t][k] * W_ih[j][k]
// Block tile: 64 t  x 128 j  x 32 k.  K split in 2 via blockIdx.y (to get
// 128 blocks for 148 SMs).  256 threads; each thread computes 4t x 8j.
// Tiles staged k-major in smem so the inner loop is pure float4 LDS + FFMA.
// ---------------------------------------------------------------------------
__global__ void __launch_bounds__(256) k_phase1(const float* __restrict__ x,
                                                const float* __restrict__ wih) {
    __shared__ float xs[32 * 68];    // [k][t], padded row 68
    __shared__ float ws[32 * 132];   // [k][j], padded row 132

    const int tid = threadIdx.x;
    const int jblock = blockIdx.x * 128;
    const int kbase0 = blockIdx.y * (H / 2);

    // compute mapping
    const int tx = tid & 15;         // j group: j0 = tx*8
    const int ty = tid >> 4;         // t group: t0 = ty*4
    const int j0 = tx * 8;
    const int t0 = ty * 4;

    // loader mapping
    const int lt = tid & 7;          // k quad: k = lt*4 .. +3
    const int lr = tid >> 3;         // 0..31

    float acc[4][8];
#pragma unroll
    for (int i = 0; i < 4; ++i)
#pragma unroll
        for (int j = 0; j < 8; ++j) acc[i][j] = 0.f;

    for (int kt = 0; kt < (H / 2) / 32; ++kt) {
        const int kb = kbase0 + kt * 32;

        // load x tile: 64t x 32k, transposed into xs[k][t]
        {
            float4 v0 = *reinterpret_cast<const float4*>(x + (size_t)lr * H + kb + lt * 4);
            float4 v1 = *reinterpret_cast<const float4*>(x + (size_t)(lr + 32) * H + kb + lt * 4);
            xs[(lt * 4 + 0) * 68 + lr] = v0.x;
            xs[(lt * 4 + 1) * 68 + lr] = v0.y;
            xs[(lt * 4 + 2) * 68 + lr] = v0.z;
            xs[(lt * 4 + 3) * 68 + lr] = v0.w;
            xs[(lt * 4 + 0) * 68 + lr + 32] = v1.x;
            xs[(lt * 4 + 1) * 68 + lr + 32] = v1.y;
            xs[(lt * 4 + 2) * 68 + lr + 32] = v1.z;
            xs[(lt * 4 + 3) * 68 + lr + 32] = v1.w;
        }
        // load W_ih tile: 128j x 32k, transposed into ws[k][j]
#pragma unroll
        for (int m = 0; m < 4; ++m) {
            int j = lr + m * 32;
            float4 v = *reinterpret_cast<const float4*>(wih + (size_t)(jblock + j) * H + kb + lt * 4);
            ws[(lt * 4 + 0) * 132 + j] = v.x;
            ws[(lt * 4 + 1) * 132 + j] = v.y;
            ws[(lt * 4 + 2) * 132 + j] = v.z;
            ws[(lt * 4 + 3) * 132 + j] = v.w;
        }
        __syncthreads();

#pragma unroll
        for (int k = 0; k < 32; ++k) {
            float4 xv = *reinterpret_cast<const float4*>(xs + k * 68 + t0);
            float4 wa = *reinterpret_cast<const float4*>(ws + k * 132 + j0);
            float4 wb = *reinterpret_cast<const float4*>(ws + k * 132 + j0 + 4);
            float xr[4] = {xv.x, xv.y, xv.z, xv.w};
            float wr[8] = {wa.x, wa.y, wa.z, wa.w, wb.x, wb.y, wb.z, wb.w};
#pragma unroll
            for (int i = 0; i < 4; ++i)
#pragma unroll
                for (int j = 0; j < 8; ++j)
                    acc[i][j] = fmaf(xr[i], wr[j], acc[i][j]);
        }
        __syncthreads();
    }

    float* dst = (blockIdx.y == 0) ? g_pre0 : g_pre1;
#pragma unroll
    for (int i = 0; i < 4; ++i) {
        float4 oa = make_float4(acc[i][0], acc[i][1], acc[i][2], acc[i][3]);
        float4 ob = make_float4(acc[i][4], acc[i][5], acc[i][6], acc[i][7]);
        *reinterpret_cast<float4*>(dst + (size_t)(t0 + i) * H + jblock + j0) = oa;
        *reinterpret_cast<float4*>(dst + (size_t)(t0 + i) * H + jblock + j0 + 4) = ob;
    }
}

// ---------------------------------------------------------------------------
// K3a: step 0 (h_prev = 0):  out[0][j] = tanh(pre[0][j] + b[j])
// ---------------------------------------------------------------------------
__global__ void __launch_bounds__(256) k_step0(float* __restrict__ out,
                                               const float* __restrict__ b) {
    int j = blockIdx.x * 256 + threadIdx.x;
    out[j] = tanhf(g_pre0[j] + g_pre1[j] + b[j]);
}

// ---------------------------------------------------------------------------
// K3: recurrent step t:
//   out[t][j] = tanh(pre[t][j] + b[j] + sum_k h_prev[k] * Whh_f16[j][k])
// 256 threads = 8 warps; 1 warp per output row; h_prev staged in smem.
// Memory-bound: 128 MB fp16 weight stream per step.
// ---------------------------------------------------------------------------
__global__ void __launch_bounds__(256) k_step(const float* __restrict__ hprev,
                                              float* __restrict__ hout,
                                              const float* __restrict__ b,
                                              int t) {
    __shared__ float hs[H];   // 32 KB

    // cooperative vectorized load of h_prev
    for (int i = threadIdx.x * 4; i < H; i += 256 * 4)
        *reinterpret_cast<float4*>(hs + i) = *reinterpret_cast<const float4*>(hprev + i);
    __syncthreads();

    const int warp = threadIdx.x >> 5;
    const int lane = threadIdx.x & 31;
    const int j = blockIdx.x * 8 + warp;
    const __half* wrow = g_whh + (size_t)j * H;

    float sum0 = 0.f, sum1 = 0.f;
#pragma unroll 4
    for (int it = 0; it < 32; ++it) {
        int k = (it * 32 + lane) * 8;
        uint4 w = *reinterpret_cast<const uint4*>(wrow + k);
        __half2 a0 = reinterpret_cast<__half2&>(w.x);
        __half2 a1 = reinterpret_cast<__half2&>(w.y);
        __half2 a2 = reinterpret_cast<__half2&>(w.z);
        __half2 a3 = reinterpret_cast<__half2&>(w.w);
        float2 f0 = __half22float2(a0);
        float2 f1 = __half22float2(a1);
        float2 f2 = __half22float2(a2);
        float2 f3 = __half22float2(a3);
        float4 hA = *reinterpret_cast<const float4*>(hs + k);
        float4 hB = *reinterpret_cast<const float4*>(hs + k + 4);
        sum0 = fmaf(f0.x, hA.x, sum0);
        sum1 = fmaf(f0.y, hA.y, sum1);
        sum0 = fmaf(f1.x, hA.z, sum0);
        sum1 = fmaf(f1.y, hA.w, sum1);
        sum0 = fmaf(f2.x, hB.x, sum0);
        sum1 = fmaf(f2.y, hB.y, sum1);
        sum0 = fmaf(f3.x, hB.z, sum0);
        sum1 = fmaf(f3.y, hB.w, sum1);
    }
    float sum = sum0 + sum1;
#pragma unroll
    for (int off = 16; off > 0; off >>= 1)
        sum += __shfl_xor_sync(0xFFFFFFFFu, sum, off);

    if (lane == 0) {
        const float* p0 = g_pre0 + (size_t)t * H;
        const float* p1 = g_pre1 + (size_t)t * H;
        hout[j] = tanhf(sum + p0[j] + p1[j] + b[j]);
    }
}

// ---------------------------------------------------------------------------
extern "C" void kernel_launch(void* const* d_in, const int* in_sizes, int n_in,
                              void* d_out, int out_size) {
    const float* x   = (const float*)d_in[0];   // (64, 8192)
    const float* wih = (const float*)d_in[1];   // (8192, 8192)
    const float* whh = (const float*)d_in[2];   // (8192, 8192)
    const float* b   = (const float*)d_in[3];   // (8192,)
    float* out = (float*)d_out;                 // 64*8192 = 4096*128

    // 1) W_hh -> fp16 scratch
    k_convert<<<(H * (size_t)H) / 8 / 256, 256>>>(whh);

    // 2) pre[t] = x_t . W_ih^T   (K split in 2 -> 128 blocks)
    k_phase1<<<dim3(H / 128, 2), 256>>>(x, wih);

    // 3) recurrence; h_t lives directly in the output rows
    k_step0<<<H / 256, 256>>>(out, b);
    for (int t = 1; t < T; ++t)
        k_step<<<H / 8, 256>>>(out + (size_t)(t - 1) * H,
                               out + (size_t)t * H, b, t);
}

// round 7
// speedup vs baseline: 1.1902x; 1.1902x over previous
#include <cuda_runtime.h>
#include <cuda_fp16.h>

#define H 8192
#define T 64

// Scratch (device globals: sanctioned allocation-free workaround).
__device__ __half g_whh[(size_t)H * (size_t)H];   // fp16 W_hh, 128 MiB
__device__ float g_pre0[T * H];                   // K-split halves of x_t . W_ih^T
__device__ float g_pre1[T * H];

// ---------------------------------------------------------------------------
// K1: convert W_hh fp32 -> fp16 (384 MB traffic, ~55 us)
// ---------------------------------------------------------------------------
__global__ void __launch_bounds__(256) k_convert(const float* __restrict__ whh) {
    size_t i = ((size_t)blockIdx.x * 256u + threadIdx.x) * 8u;
    float4 a = *reinterpret_cast<const float4*>(whh + i);
    float4 c = *reinterpret_cast<const float4*>(whh + i + 4);
    __half2 h0 = __floats2half2_rn(a.x, a.y);
    __half2 h1 = __floats2half2_rn(a.z, a.w);
    __half2 h2 = __floats2half2_rn(c.x, c.y);
    __half2 h3 = __floats2half2_rn(c.z, c.w);
    uint4 o;
    o.x = reinterpret_cast<unsigned int&>(h0);
    o.y = reinterpret_cast<unsigned int&>(h1);
    o.z = reinterpret_cast<unsigned int&>(h2);
    o.w = reinterpret_cast<unsigned int&>(h3);
    *reinterpret_cast<uint4*>(g_whh + i) = o;
}

// ---------------------------------------------------------------------------
// K2: phase-1 SGEMM  pre[t][j] = sum_k x[t][k] * W_ih[j][k]   (unchanged)
// ---------------------------------------------------------------------------
__global__ void __launch_bounds__(256) k_phase1(const float* __restrict__ x,
                                                const float* __restrict__ wih) {
    __shared__ float xs[32 * 68];
    __shared__ float ws[32 * 132];

    const int tid = threadIdx.x;
    const int jblock = blockIdx.x * 128;
    const int kbase0 = blockIdx.y * (H / 2);

    const int tx = tid & 15;
    const int ty = tid >> 4;
    const int j0 = tx * 8;
    const int t0 = ty * 4;

    const int lt = tid & 7;
    const int lr = tid >> 3;

    float acc[4][8];
#pragma unroll
    for (int i = 0; i < 4; ++i)
#pragma unroll
        for (int j = 0; j < 8; ++j) acc[i][j] = 0.f;

    for (int kt = 0; kt < (H / 2) / 32; ++kt) {
        const int kb = kbase0 + kt * 32;
        {
            float4 v0 = *reinterpret_cast<const float4*>(x + (size_t)lr * H + kb + lt * 4);
            float4 v1 = *reinterpret_cast<const float4*>(x + (size_t)(lr + 32) * H + kb + lt * 4);
            xs[(lt * 4 + 0) * 68 + lr] = v0.x;
            xs[(lt * 4 + 1) * 68 + lr] = v0.y;
            xs[(lt * 4 + 2) * 68 + lr] = v0.z;
            xs[(lt * 4 + 3) * 68 + lr] = v0.w;
            xs[(lt * 4 + 0) * 68 + lr + 32] = v1.x;
            xs[(lt * 4 + 1) * 68 + lr + 32] = v1.y;
            xs[(lt * 4 + 2) * 68 + lr + 32] = v1.z;
            xs[(lt * 4 + 3) * 68 + lr + 32] = v1.w;
        }
#pragma unroll
        for (int m = 0; m < 4; ++m) {
            int j = lr + m * 32;
            float4 v = *reinterpret_cast<const float4*>(wih + (size_t)(jblock + j) * H + kb + lt * 4);
            ws[(lt * 4 + 0) * 132 + j] = v.x;
            ws[(lt * 4 + 1) * 132 + j] = v.y;
            ws[(lt * 4 + 2) * 132 + j] = v.z;
            ws[(lt * 4 + 3) * 132 + j] = v.w;
        }
        __syncthreads();

#pragma unroll
        for (int k = 0; k < 32; ++k) {
            float4 xv = *reinterpret_cast<const float4*>(xs + k * 68 + t0);
            float4 wa = *reinterpret_cast<const float4*>(ws + k * 132 + j0);
            float4 wb = *reinterpret_cast<const float4*>(ws + k * 132 + j0 + 4);
            float xr[4] = {xv.x, xv.y, xv.z, xv.w};
            float wr[8] = {wa.x, wa.y, wa.z, wa.w, wb.x, wb.y, wb.z, wb.w};
#pragma unroll
            for (int i = 0; i < 4; ++i)
#pragma unroll
                for (int j = 0; j < 8; ++j)
                    acc[i][j] = fmaf(xr[i], wr[j], acc[i][j]);
        }
        __syncthreads();
    }

    float* dst = (blockIdx.y == 0) ? g_pre0 : g_pre1;
#pragma unroll
    for (int i = 0; i < 4; ++i) {
        float4 oa = make_float4(acc[i][0], acc[i][1], acc[i][2], acc[i][3]);
        float4 ob = make_float4(acc[i][4], acc[i][5], acc[i][6], acc[i][7]);
        *reinterpret_cast<float4*>(dst + (size_t)(t0 + i) * H + jblock + j0) = oa;
        *reinterpret_cast<float4*>(dst + (size_t)(t0 + i) * H + jblock + j0 + 4) = ob;
    }
}

// ---------------------------------------------------------------------------
// K3a: step 0 (h_prev = 0)
// ---------------------------------------------------------------------------
__global__ void __launch_bounds__(256) k_step0(float* __restrict__ out,
                                               const float* __restrict__ b) {
    int j = blockIdx.x * 256 + threadIdx.x;
    out[j] = tanhf(g_pre0[j] + g_pre1[j] + b[j]);
}

// ---------------------------------------------------------------------------
// K3: recurrent step (REWORKED: k-split across warps, register-resident h).
//
// Block = 256 threads = 8 warps; block computes 8 output rows.
// Warp w owns k in [w*1024, (w+1)*1024); lane holds its 32 h values in regs.
// Per row per warp: 4 independent LDG.128 of fp16 weights + 32 FFMA on
// register h + shfl reduce -> smem partial[row][warp]; one barrier; 8
// threads finalize tanh.  No LDS in the hot loop, 256 B smem, grid 1024
// (~3.5 waves at 2-3 CTAs/SM) -> good tail smoothing + deep MLP.
// ---------------------------------------------------------------------------
__global__ void __launch_bounds__(256, 2) k_step(const float* __restrict__ hprev,
                                                 float* __restrict__ hout,
                                                 const float* __restrict__ b,
                                                 int t) {
    __shared__ float part[8][8];   // [row][warp]

    const int warp = threadIdx.x >> 5;
    const int lane = threadIdx.x & 31;
    const int k0 = warp * 1024 + lane * 8;

    // Preload this lane's h slice into registers: h[k0 + it*256 + 0..7]
    float hr[4][8];
#pragma unroll
    for (int it = 0; it < 4; ++it) {
        float4 a = *reinterpret_cast<const float4*>(hprev + k0 + it * 256);
        float4 c = *reinterpret_cast<const float4*>(hprev + k0 + it * 256 + 4);
        hr[it][0] = a.x; hr[it][1] = a.y; hr[it][2] = a.z; hr[it][3] = a.w;
        hr[it][4] = c.x; hr[it][5] = c.y; hr[it][6] = c.z; hr[it][7] = c.w;
    }

    const int jbase = blockIdx.x * 8;

#pragma unroll 2
    for (int r = 0; r < 8; ++r) {
        const __half* wrow = g_whh + (size_t)(jbase + r) * H + k0;
        float s0 = 0.f, s1 = 0.f;
#pragma unroll
        for (int it = 0; it < 4; ++it) {
            uint4 w = *reinterpret_cast<const uint4*>(wrow + it * 256);
            float2 f0 = __half22float2(reinterpret_cast<__half2&>(w.x));
            float2 f1 = __half22float2(reinterpret_cast<__half2&>(w.y));
            float2 f2 = __half22float2(reinterpret_cast<__half2&>(w.z));
            float2 f3 = __half22float2(reinterpret_cast<__half2&>(w.w));
            s0 = fmaf(f0.x, hr[it][0], s0);
            s1 = fmaf(f0.y, hr[it][1], s1);
            s0 = fmaf(f1.x, hr[it][2], s0);
            s1 = fmaf(f1.y, hr[it][3], s1);
            s0 = fmaf(f2.x, hr[it][4], s0);
            s1 = fmaf(f2.y, hr[it][5], s1);
            s0 = fmaf(f3.x, hr[it][6], s0);
            s1 = fmaf(f3.y, hr[it][7], s1);
        }
        float s = s0 + s1;
#pragma unroll
        for (int off = 16; off > 0; off >>= 1)
            s += __shfl_xor_sync(0xFFFFFFFFu, s, off);
        if (lane == 0) part[r][warp] = s;
    }
    __syncthreads();

    if (threadIdx.x < 8) {
        const int j = jbase + threadIdx.x;
        float s = part[threadIdx.x][0] + part[threadIdx.x][1] +
                  part[threadIdx.x][2] + part[threadIdx.x][3] +
                  part[threadIdx.x][4] + part[threadIdx.x][5] +
                  part[threadIdx.x][6] + part[threadIdx.x][7];
        hout[j] = tanhf(s + g_pre0[(size_t)t * H + j] +
                            g_pre1[(size_t)t * H + j] + b[j]);
    }
}

// ---------------------------------------------------------------------------
extern "C" void kernel_launch(void* const* d_in, const int* in_sizes, int n_in,
                              void* d_out, int out_size) {
    const float* x   = (const float*)d_in[0];   // (64, 8192)
    const float* wih = (const float*)d_in[1];   // (8192, 8192)
    const float* whh = (const float*)d_in[2];   // (8192, 8192)
    const float* b   = (const float*)d_in[3];   // (8192,)
    float* out = (float*)d_out;                 // 64*8192

    k_convert<<<(H * (size_t)H) / 8 / 256, 256>>>(whh);
    k_phase1<<<dim3(H / 128, 2), 256>>>(x, wih);
    k_step0<<<H / 256, 256>>>(out, b);
    for (int t = 1; t < T; ++t)
        k_step<<<H / 8, 256>>>(out + (size_t)(t - 1) * H,
                               out + (size_t)t * H, b, t);
}

// round 9
// speedup vs baseline: 1.4798x; 1.2434x over previous
#include <cuda_runtime.h>
#include <cuda_fp16.h>

#define H 8192
#define T 64

// Scratch (device globals: sanctioned allocation-free workaround).
__device__ __half g_whh[(size_t)H * (size_t)H];   // fp16 W_hh, 128 MiB
__device__ float g_pre0[T * H];                   // K-split halves of x_t . W_ih^T
__device__ float g_pre1[T * H];

// ---------------------------------------------------------------------------
// K1: convert W_hh fp32 -> fp16 (384 MB traffic, ~55 us)
// ---------------------------------------------------------------------------
__global__ void __launch_bounds__(256) k_convert(const float* __restrict__ whh) {
    size_t i = ((size_t)blockIdx.x * 256u + threadIdx.x) * 8u;
    float4 a = *reinterpret_cast<const float4*>(whh + i);
    float4 c = *reinterpret_cast<const float4*>(whh + i + 4);
    __half2 h0 = __floats2half2_rn(a.x, a.y);
    __half2 h1 = __floats2half2_rn(a.z, a.w);
    __half2 h2 = __floats2half2_rn(c.x, c.y);
    __half2 h3 = __floats2half2_rn(c.z, c.w);
    uint4 o;
    o.x = reinterpret_cast<unsigned int&>(h0);
    o.y = reinterpret_cast<unsigned int&>(h1);
    o.z = reinterpret_cast<unsigned int&>(h2);
    o.w = reinterpret_cast<unsigned int&>(h3);
    *reinterpret_cast<uint4*>(g_whh + i) = o;
}

// ---------------------------------------------------------------------------
// K2: phase-1 SGEMM  pre[t][j] = sum_k x[t][k] * W_ih[j][k]   (unchanged)
// ---------------------------------------------------------------------------
__global__ void __launch_bounds__(256) k_phase1(const float* __restrict__ x,
                                                const float* __restrict__ wih) {
    __shared__ float xs[32 * 68];
    __shared__ float ws[32 * 132];

    const int tid = threadIdx.x;
    const int jblock = blockIdx.x * 128;
    const int kbase0 = blockIdx.y * (H / 2);

    const int tx = tid & 15;
    const int ty = tid >> 4;
    const int j0 = tx * 8;
    const int t0 = ty * 4;

    const int lt = tid & 7;
    const int lr = tid >> 3;

    float acc[4][8];
#pragma unroll
    for (int i = 0; i < 4; ++i)
#pragma unroll
        for (int j = 0; j < 8; ++j) acc[i][j] = 0.f;

    for (int kt = 0; kt < (H / 2) / 32; ++kt) {
        const int kb = kbase0 + kt * 32;
        {
            float4 v0 = *reinterpret_cast<const float4*>(x + (size_t)lr * H + kb + lt * 4);
            float4 v1 = *reinterpret_cast<const float4*>(x + (size_t)(lr + 32) * H + kb + lt * 4);
            xs[(lt * 4 + 0) * 68 + lr] = v0.x;
            xs[(lt * 4 + 1) * 68 + lr] = v0.y;
            xs[(lt * 4 + 2) * 68 + lr] = v0.z;
            xs[(lt * 4 + 3) * 68 + lr] = v0.w;
            xs[(lt * 4 + 0) * 68 + lr + 32] = v1.x;
            xs[(lt * 4 + 1) * 68 + lr + 32] = v1.y;
            xs[(lt * 4 + 2) * 68 + lr + 32] = v1.z;
            xs[(lt * 4 + 3) * 68 + lr + 32] = v1.w;
        }
#pragma unroll
        for (int m = 0; m < 4; ++m) {
            int j = lr + m * 32;
            float4 v = *reinterpret_cast<const float4*>(wih + (size_t)(jblock + j) * H + kb + lt * 4);
            ws[(lt * 4 + 0) * 132 + j] = v.x;
            ws[(lt * 4 + 1) * 132 + j] = v.y;
            ws[(lt * 4 + 2) * 132 + j] = v.z;
            ws[(lt * 4 + 3) * 132 + j] = v.w;
        }
        __syncthreads();

#pragma unroll
        for (int k = 0; k < 32; ++k) {
            float4 xv = *reinterpret_cast<const float4*>(xs + k * 68 + t0);
            float4 wa = *reinterpret_cast<const float4*>(ws + k * 132 + j0);
            float4 wb = *reinterpret_cast<const float4*>(ws + k * 132 + j0 + 4);
            float xr[4] = {xv.x, xv.y, xv.z, xv.w};
            float wr[8] = {wa.x, wa.y, wa.z, wa.w, wb.x, wb.y, wb.z, wb.w};
#pragma unroll
            for (int i = 0; i < 4; ++i)
#pragma unroll
                for (int j = 0; j < 8; ++j)
                    acc[i][j] = fmaf(xr[i], wr[j], acc[i][j]);
        }
        __syncthreads();
    }

    float* dst = (blockIdx.y == 0) ? g_pre0 : g_pre1;
#pragma unroll
    for (int i = 0; i < 4; ++i) {
        float4 oa = make_float4(acc[i][0], acc[i][1], acc[i][2], acc[i][3]);
        float4 ob = make_float4(acc[i][4], acc[i][5], acc[i][6], acc[i][7]);
        *reinterpret_cast<float4*>(dst + (size_t)(t0 + i) * H + jblock + j0) = oa;
        *reinterpret_cast<float4*>(dst + (size_t)(t0 + i) * H + jblock + j0 + 4) = ob;
    }
}

// ---------------------------------------------------------------------------
// K3a: step 0 (h_prev = 0)
// ---------------------------------------------------------------------------
__global__ void __launch_bounds__(256) k_step0(float* __restrict__ out,
                                               const float* __restrict__ b) {
    int j = blockIdx.x * 256 + threadIdx.x;
    out[j] = tanhf(g_pre0[j] + g_pre1[j] + b[j]);
}

// ---------------------------------------------------------------------------
// K3: recurrent step (k-split across warps, register-resident h,
//     batched 8-row accumulation + one combined shuffle reduce,
//     alternating traversal direction for L2 rocking).
//
// Block = 256 threads = 8 warps; block computes 8 output rows.
// Warp w owns k in [w*1024, (w+1)*1024); lane holds its 32 h values in regs.
// Inner structure: outer loop over 4 k-iterations, inner loop over 8 rows
// -> 8 independent LDG.128 in flight per warp per k-iter, h reused from
// registers, one accumulator per row.  Reduction: 5 rounds x 8 independent
// shfls (pipelined) instead of per-row serialized trees.
//
// `rev` flips the block->row mapping each step: fp16 W_hh (128 MiB) vs L2
// (~126 MB) means a reversed traversal re-reads the previous step's cached
// tail first -> most weight reads hit L2 (~12 TB/s fabric) instead of DRAM.
// ---------------------------------------------------------------------------
__global__ void __launch_bounds__(256, 2) k_step(const float* __restrict__ hprev,
                                                 float* __restrict__ hout,
                                                 const float* __restrict__ b,
                                                 int t, int rev) {
    __shared__ float part[8][8];   // [row][warp]

    const int warp = threadIdx.x >> 5;
    const int lane = threadIdx.x & 31;
    const int k0 = warp * 1024 + lane * 8;

    // Preload this lane's h slice into registers: h[k0 + it*256 + 0..7]
    float hr[4][8];
#pragma unroll
    for (int it = 0; it < 4; ++it) {
        float4 a = *reinterpret_cast<const float4*>(hprev + k0 + it * 256);
        float4 c = *reinterpret_cast<const float4*>(hprev + k0 + it * 256 + 4);
        hr[it][0] = a.x; hr[it][1] = a.y; hr[it][2] = a.z; hr[it][3] = a.w;
        hr[it][4] = c.x; hr[it][5] = c.y; hr[it][6] = c.z; hr[it][7] = c.w;
    }

    const int blk = rev ? ((int)gridDim.x - 1 - blockIdx.x) : blockIdx.x;
    const int jbase = blk * 8;
    const __half* wbase = g_whh + (size_t)jbase * H + k0;

    float s[8];
#pragma unroll
    for (int r = 0; r < 8; ++r) s[r] = 0.f;

#pragma unroll
    for (int it = 0; it < 4; ++it) {
#pragma unroll
        for (int r = 0; r < 8; ++r) {
            uint4 w = *reinterpret_cast<const uint4*>(wbase + (size_t)r * H + it * 256);
            float2 f0 = __half22float2(reinterpret_cast<__half2&>(w.x));
            float2 f1 = __half22float2(reinterpret_cast<__half2&>(w.y));
            float2 f2 = __half22float2(reinterpret_cast<__half2&>(w.z));
            float2 f3 = __half22float2(reinterpret_cast<__half2&>(w.w));
            float acc = s[r];
            acc = fmaf(f0.x, hr[it][0], acc);
            acc = fmaf(f0.y, hr[it][1], acc);
            acc = fmaf(f1.x, hr[it][2], acc);
            acc = fmaf(f1.y, hr[it][3], acc);
            acc = fmaf(f2.x, hr[it][4], acc);
            acc = fmaf(f2.y, hr[it][5], acc);
            acc = fmaf(f3.x, hr[it][6], acc);
            acc = fmaf(f3.y, hr[it][7], acc);
            s[r] = acc;
        }
    }

    // Batched butterfly reduce: 5 rounds x 8 independent shfls.
#pragma unroll
    for (int off = 16; off > 0; off >>= 1)
#pragma unroll
        for (int r = 0; r < 8; ++r)
            s[r] += __shfl_xor_sync(0xFFFFFFFFu, s[r], off);

    if (lane == 0) {
#pragma unroll
        for (int r = 0; r < 8; ++r) part[r][warp] = s[r];
    }
    __syncthreads();

    if (threadIdx.x < 8) {
        const int j = jbase + threadIdx.x;
        float v = part[threadIdx.x][0] + part[threadIdx.x][1] +
                  part[threadIdx.x][2] + part[threadIdx.x][3] +
                  part[threadIdx.x][4] + part[threadIdx.x][5] +
                  part[threadIdx.x][6] + part[threadIdx.x][7];
        hout[j] = tanhf(v + g_pre0[(size_t)t * H + j] +
                            g_pre1[(size_t)t * H + j] + b[j]);
    }
}

// ---------------------------------------------------------------------------
extern "C" void kernel_launch(void* const* d_in, const int* in_sizes, int n_in,
                              void* d_out, int out_size) {
    const float* x   = (const float*)d_in[0];   // (64, 8192)
    const float* wih = (const float*)d_in[1];   // (8192, 8192)
    const float* whh = (const float*)d_in[2];   // (8192, 8192)
    const float* b   = (const float*)d_in[3];   // (8192,)
    float* out = (float*)d_out;                 // 64*8192

    k_convert<<<(H * (size_t)H) / 8 / 256, 256>>>(whh);
    k_phase1<<<dim3(H / 128, 2), 256>>>(x, wih);
    k_step0<<<H / 256, 256>>>(out, b);
    for (int t = 1; t < T; ++t)
        k_step<<<H / 8, 256>>>(out + (size_t)(t - 1) * H,
                               out + (size_t)t * H, b, t, t & 1);
}

// round 12
// speedup vs baseline: 1.5913x; 1.0753x over previous
#include <cuda_runtime.h>
#include <cuda_fp16.h>
#include <cstdint>

#define H 8192
#define T 64

// Scratch (device globals: sanctioned allocation-free workaround).
__device__ __half g_whh[(size_t)H * (size_t)H];   // fp16 W_hh, 128 MiB
__device__ float g_pre[T * H];                    // pre[t][j] = x_t . W_ih^T

// ---------------------------------------------------------------------------
// K1: convert W_hh fp32 -> fp16.  256-bit stores tagged L2::evict_last
// (ptxas requires v8.b32 with that modifier) so the weight image is
// L2-resident (~126MB pinned by priority) for the recurrence.
// One thread per 16 elements.
// ---------------------------------------------------------------------------
__global__ void __launch_bounds__(256) k_convert(const float* __restrict__ whh) {
    size_t i = ((size_t)blockIdx.x * 256u + threadIdx.x) * 16u;
    uint32_t o[8];
#pragma unroll
    for (int q = 0; q < 4; ++q) {
        float4 a = *reinterpret_cast<const float4*>(whh + i + q * 4);
        __half2 lo = __floats2half2_rn(a.x, a.y);
        __half2 hi = __floats2half2_rn(a.z, a.w);
        o[q * 2 + 0] = reinterpret_cast<unsigned int&>(lo);
        o[q * 2 + 1] = reinterpret_cast<unsigned int&>(hi);
    }
    asm volatile("st.global.L2::evict_last.v8.b32 [%0], {%1,%2,%3,%4,%5,%6,%7,%8};"
                 :: "l"(g_whh + i),
                    "r"(o[0]), "r"(o[1]), "r"(o[2]), "r"(o[3]),
                    "r"(o[4]), "r"(o[5]), "r"(o[6]), "r"(o[7])
                 : "memory");
}

// ---------------------------------------------------------------------------
// tf32 mma helpers
// ---------------------------------------------------------------------------
__device__ __forceinline__ uint32_t f2tf(float f) {
    uint32_t u;
    asm("cvt.rna.tf32.f32 %0, %1;" : "=r"(u) : "f"(f));
    return u;
}
__device__ __forceinline__ void mma_tf32(float* c,
                                         uint32_t a0, uint32_t a1, uint32_t a2, uint32_t a3,
                                         uint32_t b0, uint32_t b1) {
    asm volatile("mma.sync.aligned.m16n8k8.row.col.f32.tf32.tf32.f32 "
                 "{%0,%1,%2,%3}, {%4,%5,%6,%7}, {%8,%9}, {%0,%1,%2,%3};"
                 : "+f"(c[0]), "+f"(c[1]), "+f"(c[2]), "+f"(c[3])
                 : "r"(a0), "r"(a1), "r"(a2), "r"(a3), "r"(b0), "r"(b1));
}

// ---------------------------------------------------------------------------
// K2: phase-1 GEMM on tensor cores (tf32):  pre[t][j] = sum_k x[t][k]*W_ih[j][k]
// Block: 64 t x 64 j, full K.  8 warps in 2(m) x 4(n); warp tile 32x16
// (2x2 m16n8k8 mma tiles).  K staged in chunks of 32 fp32, smem rows padded
// to 36 floats -> conflict-free per-thread fragment LDS.
// Grid = 128 blocks (~1 wave on 148 SMs).
// ---------------------------------------------------------------------------
__global__ void __launch_bounds__(256) k_phase1(const float* __restrict__ x,
                                                const float* __restrict__ wih) {
    __shared__ float As[64 * 36];   // [t][k], row pad 36
    __shared__ float Bs[64 * 36];   // [j][k], row pad 36

    const int tid = threadIdx.x;
    const int warp = tid >> 5;
    const int lane = tid & 31;
    const int wm = warp >> 2;            // 0..1  -> m rows 32*wm
    const int wn = warp & 3;             // 0..3  -> n cols 16*wn
    const int g = lane >> 2;             // groupID 0..7
    const int tig = lane & 3;            // threadID_in_group
    const int jb = blockIdx.x * 64;

    float acc[2][2][4];
#pragma unroll
    for (int mt = 0; mt < 2; ++mt)
#pragma unroll
        for (int nt = 0; nt < 2; ++nt)
#pragma unroll
            for (int i = 0; i < 4; ++i) acc[mt][nt][i] = 0.f;

    for (int kc = 0; kc < H; kc += 32) {
        // Stage A (x) and B (W_ih): 64 rows x 32 floats each = 512 float4 each.
#pragma unroll
        for (int p = 0; p < 2; ++p) {
            int idx = tid + p * 256;        // 0..511
            int r = idx >> 3;
            int c4 = (idx & 7) * 4;
            float4 v = *reinterpret_cast<const float4*>(x + (size_t)r * H + kc + c4);
            *reinterpret_cast<float4*>(As + r * 36 + c4) = v;
            float4 w = *reinterpret_cast<const float4*>(wih + (size_t)(jb + r) * H + kc + c4);
            *reinterpret_cast<float4*>(Bs + r * 36 + c4) = w;
        }
        __syncthreads();

#pragma unroll
        for (int ks = 0; ks < 4; ++ks) {
            const int k0 = ks * 8;
            // A fragments for the 2 m-tiles
            uint32_t a[2][4];
#pragma unroll
            for (int mt = 0; mt < 2; ++mt) {
                int mr = wm * 32 + mt * 16;
                a[mt][0] = f2tf(As[(mr + g)     * 36 + k0 + tig]);
                a[mt][1] = f2tf(As[(mr + g + 8) * 36 + k0 + tig]);
                a[mt][2] = f2tf(As[(mr + g)     * 36 + k0 + tig + 4]);
                a[mt][3] = f2tf(As[(mr + g + 8) * 36 + k0 + tig + 4]);
            }
            // B fragments for the 2 n-tiles
            uint32_t bfr[2][2];
#pragma unroll
            for (int nt = 0; nt < 2; ++nt) {
                int nr = wn * 16 + nt * 8;
                bfr[nt][0] = f2tf(Bs[(nr + g) * 36 + k0 + tig]);
                bfr[nt][1] = f2tf(Bs[(nr + g) * 36 + k0 + tig + 4]);
            }
#pragma unroll
            for (int mt = 0; mt < 2; ++mt)
#pragma unroll
                for (int nt = 0; nt < 2; ++nt)
                    mma_tf32(acc[mt][nt], a[mt][0], a[mt][1], a[mt][2], a[mt][3],
                             bfr[nt][0], bfr[nt][1]);
        }
        __syncthreads();
    }

    // Epilogue: scatter accumulators to g_pre[t][j]
#pragma unroll
    for (int mt = 0; mt < 2; ++mt) {
        int t0 = wm * 32 + mt * 16 + g;
#pragma unroll
        for (int nt = 0; nt < 2; ++nt) {
            int j0 = jb + wn * 16 + nt * 8 + tig * 2;
            *reinterpret_cast<float2*>(g_pre + (size_t)t0 * H + j0) =
                make_float2(acc[mt][nt][0], acc[mt][nt][1]);
            *reinterpret_cast<float2*>(g_pre + (size_t)(t0 + 8) * H + j0) =
                make_float2(acc[mt][nt][2], acc[mt][nt][3]);
        }
    }
}

// ---------------------------------------------------------------------------
// K3a: step 0 (h_prev = 0)
// ---------------------------------------------------------------------------
__global__ void __launch_bounds__(256) k_step0(float* __restrict__ out,
                                               const float* __restrict__ b) {
    int j = blockIdx.x * 256 + threadIdx.x;
    out[j] = tanhf(g_pre[j] + b[j]);
}

// ---------------------------------------------------------------------------
// K3: recurrent step.  k-split across warps, register-resident h, batched
// 8-row accumulation + combined shuffle reduce.  Weight loads are 256-bit
// (v8.b32 — required by ptxas for L2::evict_last, and halves LDG count)
// tagged evict_last so the W_hh image stays L2-resident across steps;
// traversal direction alternates per step (rocking) as belt-and-braces.
//
// Layout: warp w owns k in [w*1024, (w+1)*1024); lane owns 16 consecutive
// halves at k0 = w*1024 + lane*16, two chunks it*512 apart.
// ---------------------------------------------------------------------------
__global__ void __launch_bounds__(256, 2) k_step(const float* __restrict__ hprev,
                                                 float* __restrict__ hout,
                                                 const float* __restrict__ b,
                                                 int t, int rev) {
    __shared__ float part[8][8];   // [row][warp]

    const int warp = threadIdx.x >> 5;
    const int lane = threadIdx.x & 31;
    const int k0 = warp * 1024 + lane * 16;

    // Preload this lane's h slice into registers: h[k0 + it*512 + 0..15]
    float hr[2][16];
#pragma unroll
    for (int it = 0; it < 2; ++it) {
#pragma unroll
        for (int q = 0; q < 4; ++q) {
            float4 a = *reinterpret_cast<const float4*>(hprev + k0 + it * 512 + q * 4);
            hr[it][q * 4 + 0] = a.x;
            hr[it][q * 4 + 1] = a.y;
            hr[it][q * 4 + 2] = a.z;
            hr[it][q * 4 + 3] = a.w;
        }
    }

    const int blk = rev ? ((int)gridDim.x - 1 - blockIdx.x) : blockIdx.x;
    const int jbase = blk * 8;
    const __half* wbase = g_whh + (size_t)jbase * H + k0;

    float s[8];
#pragma unroll
    for (int r = 0; r < 8; ++r) s[r] = 0.f;

#pragma unroll
    for (int it = 0; it < 2; ++it) {
#pragma unroll
        for (int r = 0; r < 8; ++r) {
            uint32_t w0, w1, w2, w3, w4, w5, w6, w7;
            asm volatile(
                "ld.global.nc.L2::evict_last.v8.b32 "
                "{%0,%1,%2,%3,%4,%5,%6,%7}, [%8];"
                : "=r"(w0), "=r"(w1), "=r"(w2), "=r"(w3),
                  "=r"(w4), "=r"(w5), "=r"(w6), "=r"(w7)
                : "l"(wbase + (size_t)r * H + it * 512));
            float2 f0 = __half22float2(reinterpret_cast<__half2&>(w0));
            float2 f1 = __half22float2(reinterpret_cast<__half2&>(w1));
            float2 f2 = __half22float2(reinterpret_cast<__half2&>(w2));
            float2 f3 = __half22float2(reinterpret_cast<__half2&>(w3));
            float2 f4 = __half22float2(reinterpret_cast<__half2&>(w4));
            float2 f5 = __half22float2(reinterpret_cast<__half2&>(w5));
            float2 f6 = __half22float2(reinterpret_cast<__half2&>(w6));
            float2 f7 = __half22float2(reinterpret_cast<__half2&>(w7));
            float acc = s[r];
            acc = fmaf(f0.x, hr[it][0],  acc);
            acc = fmaf(f0.y, hr[it][1],  acc);
            acc = fmaf(f1.x, hr[it][2],  acc);
            acc = fmaf(f1.y, hr[it][3],  acc);
            acc = fmaf(f2.x, hr[it][4],  acc);
            acc = fmaf(f2.y, hr[it][5],  acc);
            acc = fmaf(f3.x, hr[it][6],  acc);
            acc = fmaf(f3.y, hr[it][7],  acc);
            acc = fmaf(f4.x, hr[it][8],  acc);
            acc = fmaf(f4.y, hr[it][9],  acc);
            acc = fmaf(f5.x, hr[it][10], acc);
            acc = fmaf(f5.y, hr[it][11], acc);
            acc = fmaf(f6.x, hr[it][12], acc);
            acc = fmaf(f6.y, hr[it][13], acc);
            acc = fmaf(f7.x, hr[it][14], acc);
            acc = fmaf(f7.y, hr[it][15], acc);
            s[r] = acc;
        }
    }

    // Batched butterfly reduce: 5 rounds x 8 independent shfls.
#pragma unroll
    for (int off = 16; off > 0; off >>= 1)
#pragma unroll
        for (int r = 0; r < 8; ++r)
            s[r] += __shfl_xor_sync(0xFFFFFFFFu, s[r], off);

    if (lane == 0) {
#pragma unroll
        for (int r = 0; r < 8; ++r) part[r][warp] = s[r];
    }
    __syncthreads();

    if (threadIdx.x < 8) {
        const int j = jbase + threadIdx.x;
        float v = part[threadIdx.x][0] + part[threadIdx.x][1] +
                  part[threadIdx.x][2] + part[threadIdx.x][3] +
                  part[threadIdx.x][4] + part[threadIdx.x][5] +
                  part[threadIdx.x][6] + part[threadIdx.x][7];
        hout[j] = tanhf(v + g_pre[(size_t)t * H + j] + b[j]);
    }
}

// ---------------------------------------------------------------------------
extern "C" void kernel_launch(void* const* d_in, const int* in_sizes, int n_in,
                              void* d_out, int out_size) {
    const float* x   = (const float*)d_in[0];   // (64, 8192)
    const float* wih = (const float*)d_in[1];   // (8192, 8192)
    const float* whh = (const float*)d_in[2];   // (8192, 8192)
    const float* b   = (const float*)d_in[3];   // (8192,)
    float* out = (float*)d_out;                 // 64*8192

    k_convert<<<(H * (size_t)H) / 16 / 256, 256>>>(whh);
    k_phase1<<<H / 64, 256>>>(x, wih);
    k_step0<<<H / 256, 256>>>(out, b);
    for (int t = 1; t < T; ++t)
        k_step<<<H / 8, 256>>>(out + (size_t)(t - 1) * H,
                               out + (size_t)t * H, b, t, t & 1);
}

// round 13
// speedup vs baseline: 1.6313x; 1.0251x over previous
#include <cuda_runtime.h>
#include <cuda_fp16.h>
#include <cstdint>

#define H 8192
#define T 64
// Rows of W_hh pinned L2-resident (evict_last): 5632 rows * 16KB = 88 MiB
// (~70% of the ~126MB L2).  Remaining 2560 rows (40 MiB) stream evict_first.
#define SPLIT_ROWS 5632

// Scratch (device globals: sanctioned allocation-free workaround).
__device__ __half g_whh[(size_t)H * (size_t)H];   // fp16 W_hh, 128 MiB
__device__ float g_pre[T * H];                    // pre[t][j] = x_t . W_ih^T

// ---------------------------------------------------------------------------
// K1: convert W_hh fp32 -> fp16 with 256-bit stores.  Rows < SPLIT_ROWS are
// stored L2::evict_last (pinning the resident set, and pre-warming L2);
// the rest stored L2::evict_first (pure stream, never displaces residents).
// One thread per 16 elements.
// ---------------------------------------------------------------------------
__global__ void __launch_bounds__(256) k_convert(const float* __restrict__ whh) {
    size_t i = ((size_t)blockIdx.x * 256u + threadIdx.x) * 16u;
    uint32_t o[8];
#pragma unroll
    for (int q = 0; q < 4; ++q) {
        float4 a = *reinterpret_cast<const float4*>(whh + i + q * 4);
        __half2 lo = __floats2half2_rn(a.x, a.y);
        __half2 hi = __floats2half2_rn(a.z, a.w);
        o[q * 2 + 0] = reinterpret_cast<unsigned int&>(lo);
        o[q * 2 + 1] = reinterpret_cast<unsigned int&>(hi);
    }
    if ((i >> 13) < SPLIT_ROWS) {    // row = i / H
        asm volatile("st.global.L2::evict_last.v8.b32 [%0], {%1,%2,%3,%4,%5,%6,%7,%8};"
                     :: "l"(g_whh + i),
                        "r"(o[0]), "r"(o[1]), "r"(o[2]), "r"(o[3]),
                        "r"(o[4]), "r"(o[5]), "r"(o[6]), "r"(o[7])
                     : "memory");
    } else {
        asm volatile("st.global.L2::evict_first.v8.b32 [%0], {%1,%2,%3,%4,%5,%6,%7,%8};"
                     :: "l"(g_whh + i),
                        "r"(o[0]), "r"(o[1]), "r"(o[2]), "r"(o[3]),
                        "r"(o[4]), "r"(o[5]), "r"(o[6]), "r"(o[7])
                     : "memory");
    }
}

// ---------------------------------------------------------------------------
// tf32 mma helpers
// ---------------------------------------------------------------------------
__device__ __forceinline__ uint32_t f2tf(float f) {
    uint32_t u;
    asm("cvt.rna.tf32.f32 %0, %1;" : "=r"(u) : "f"(f));
    return u;
}
__device__ __forceinline__ void mma_tf32(float* c,
                                         uint32_t a0, uint32_t a1, uint32_t a2, uint32_t a3,
                                         uint32_t b0, uint32_t b1) {
    asm volatile("mma.sync.aligned.m16n8k8.row.col.f32.tf32.tf32.f32 "
                 "{%0,%1,%2,%3}, {%4,%5,%6,%7}, {%8,%9}, {%0,%1,%2,%3};"
                 : "+f"(c[0]), "+f"(c[1]), "+f"(c[2]), "+f"(c[3])
                 : "r"(a0), "r"(a1), "r"(a2), "r"(a3), "r"(b0), "r"(b1));
}

// ---------------------------------------------------------------------------
// K2: phase-1 GEMM on tensor cores (tf32):  pre[t][j] = sum_k x[t][k]*W_ih[j][k]
// Block: 64 t x 64 j, full K.  8 warps in 2(m) x 4(n); warp tile 32x16
// (2x2 m16n8k8 mma tiles).  Grid = 128 blocks (~1 wave on 148 SMs).
// ---------------------------------------------------------------------------
__global__ void __launch_bounds__(256) k_phase1(const float* __restrict__ x,
                                                const float* __restrict__ wih) {
    __shared__ float As[64 * 36];   // [t][k], row pad 36
    __shared__ float Bs[64 * 36];   // [j][k], row pad 36

    const int tid = threadIdx.x;
    const int warp = tid >> 5;
    const int lane = tid & 31;
    const int wm = warp >> 2;            // 0..1  -> m rows 32*wm
    const int wn = warp & 3;             // 0..3  -> n cols 16*wn
    const int g = lane >> 2;             // groupID 0..7
    const int tig = lane & 3;            // threadID_in_group
    const int jb = blockIdx.x * 64;

    float acc[2][2][4];
#pragma unroll
    for (int mt = 0; mt < 2; ++mt)
#pragma unroll
        for (int nt = 0; nt < 2; ++nt)
#pragma unroll
            for (int i = 0; i < 4; ++i) acc[mt][nt][i] = 0.f;

    for (int kc = 0; kc < H; kc += 32) {
#pragma unroll
        for (int p = 0; p < 2; ++p) {
            int idx = tid + p * 256;        // 0..511
            int r = idx >> 3;
            int c4 = (idx & 7) * 4;
            float4 v = *reinterpret_cast<const float4*>(x + (size_t)r * H + kc + c4);
            *reinterpret_cast<float4*>(As + r * 36 + c4) = v;
            float4 w = *reinterpret_cast<const float4*>(wih + (size_t)(jb + r) * H + kc + c4);
            *reinterpret_cast<float4*>(Bs + r * 36 + c4) = w;
        }
        __syncthreads();

#pragma unroll
        for (int ks = 0; ks < 4; ++ks) {
            const int k0 = ks * 8;
            uint32_t a[2][4];
#pragma unroll
            for (int mt = 0; mt < 2; ++mt) {
                int mr = wm * 32 + mt * 16;
                a[mt][0] = f2tf(As[(mr + g)     * 36 + k0 + tig]);
                a[mt][1] = f2tf(As[(mr + g + 8) * 36 + k0 + tig]);
                a[mt][2] = f2tf(As[(mr + g)     * 36 + k0 + tig + 4]);
                a[mt][3] = f2tf(As[(mr + g + 8) * 36 + k0 + tig + 4]);
            }
            uint32_t bfr[2][2];
#pragma unroll
            for (int nt = 0; nt < 2; ++nt) {
                int nr = wn * 16 + nt * 8;
                bfr[nt][0] = f2tf(Bs[(nr + g) * 36 + k0 + tig]);
                bfr[nt][1] = f2tf(Bs[(nr + g) * 36 + k0 + tig + 4]);
            }
#pragma unroll
            for (int mt = 0; mt < 2; ++mt)
#pragma unroll
                for (int nt = 0; nt < 2; ++nt)
                    mma_tf32(acc[mt][nt], a[mt][0], a[mt][1], a[mt][2], a[mt][3],
                             bfr[nt][0], bfr[nt][1]);
        }
        __syncthreads();
    }

#pragma unroll
    for (int mt = 0; mt < 2; ++mt) {
        int t0 = wm * 32 + mt * 16 + g;
#pragma unroll
        for (int nt = 0; nt < 2; ++nt) {
            int j0 = jb + wn * 16 + nt * 8 + tig * 2;
            *reinterpret_cast<float2*>(g_pre + (size_t)t0 * H + j0) =
                make_float2(acc[mt][nt][0], acc[mt][nt][1]);
            *reinterpret_cast<float2*>(g_pre + (size_t)(t0 + 8) * H + j0) =
                make_float2(acc[mt][nt][2], acc[mt][nt][3]);
        }
    }
}

// ---------------------------------------------------------------------------
// K3a: step 0 (h_prev = 0)
// ---------------------------------------------------------------------------
__global__ void __launch_bounds__(256) k_step0(float* __restrict__ out,
                                               const float* __restrict__ b) {
    int j = blockIdx.x * 256 + threadIdx.x;
    out[j] = tanhf(g_pre[j] + b[j]);
}

// ---------------------------------------------------------------------------
// K3: recurrent step.  k-split across warps, register-resident h, batched
// 8-row accumulation + combined shuffle reduce.  Weight loads are 256-bit;
// rows < SPLIT_ROWS load with L2::evict_last (pinned resident set), the
// rest with L2::evict_first (stream, never displaces residents).
// ---------------------------------------------------------------------------
#define STEP_MAINLOOP(LDMOD)                                                    \
    _Pragma("unroll")                                                           \
    for (int it = 0; it < 2; ++it) {                                            \
        _Pragma("unroll")                                                       \
        for (int r = 0; r < 8; ++r) {                                           \
            uint32_t w0, w1, w2, w3, w4, w5, w6, w7;                            \
            asm volatile("ld.global.nc." LDMOD ".v8.b32 "                       \
                         "{%0,%1,%2,%3,%4,%5,%6,%7}, [%8];"                     \
                         : "=r"(w0), "=r"(w1), "=r"(w2), "=r"(w3),              \
                           "=r"(w4), "=r"(w5), "=r"(w6), "=r"(w7)               \
                         : "l"(wbase + (size_t)r * H + it * 512));              \
            float2 f0 = __half22float2(reinterpret_cast<__half2&>(w0));         \
            float2 f1 = __half22float2(reinterpret_cast<__half2&>(w1));         \
            float2 f2 = __half22float2(reinterpret_cast<__half2&>(w2));         \
            float2 f3 = __half22float2(reinterpret_cast<__half2&>(w3));         \
            float2 f4 = __half22float2(reinterpret_cast<__half2&>(w4));         \
            float2 f5 = __half22float2(reinterpret_cast<__half2&>(w5));         \
            float2 f6 = __half22float2(reinterpret_cast<__half2&>(w6));         \
            float2 f7 = __half22float2(reinterpret_cast<__half2&>(w7));         \
            float acc = s[r];                                                   \
            acc = fmaf(f0.x, hr[it][0],  acc);                                  \
            acc = fmaf(f0.y, hr[it][1],  acc);                                  \
            acc = fmaf(f1.x, hr[it][2],  acc);                                  \
            acc = fmaf(f1.y, hr[it][3],  acc);                                  \
            acc = fmaf(f2.x, hr[it][4],  acc);                                  \
            acc = fmaf(f2.y, hr[it][5],  acc);                                  \
            acc = fmaf(f3.x, hr[it][6],  acc);                                  \
            acc = fmaf(f3.y, hr[it][7],  acc);                                  \
            acc = fmaf(f4.x, hr[it][8],  acc);                                  \
            acc = fmaf(f4.y, hr[it][9],  acc);                                  \
            acc = fmaf(f5.x, hr[it][10], acc);                                  \
            acc = fmaf(f5.y, hr[it][11], acc);                                  \
            acc = fmaf(f6.x, hr[it][12], acc);                                  \
            acc = fmaf(f6.y, hr[it][13], acc);                                  \
            acc = fmaf(f7.x, hr[it][14], acc);                                  \
            acc = fmaf(f7.y, hr[it][15], acc);                                  \
            s[r] = acc;                                                         \
        }                                                                       \
    }

__global__ void __launch_bounds__(256, 2) k_step(const float* __restrict__ hprev,
                                                 float* __restrict__ hout,
                                                 const float* __restrict__ b,
                                                 int t) {
    __shared__ float part[8][8];   // [row][warp]

    const int warp = threadIdx.x >> 5;
    const int lane = threadIdx.x & 31;
    const int k0 = warp * 1024 + lane * 16;

    // Preload this lane's h slice into registers: h[k0 + it*512 + 0..15]
    float hr[2][16];
#pragma unroll
    for (int it = 0; it < 2; ++it) {
#pragma unroll
        for (int q = 0; q < 4; ++q) {
            float4 a = *reinterpret_cast<const float4*>(hprev + k0 + it * 512 + q * 4);
            hr[it][q * 4 + 0] = a.x;
            hr[it][q * 4 + 1] = a.y;
            hr[it][q * 4 + 2] = a.z;
            hr[it][q * 4 + 3] = a.w;
        }
    }

    const int jbase = blockIdx.x * 8;
    const __half* wbase = g_whh + (size_t)jbase * H + k0;

    float s[8];
#pragma unroll
    for (int r = 0; r < 8; ++r) s[r] = 0.f;

    if (jbase < SPLIT_ROWS) {
        STEP_MAINLOOP("L2::evict_last")
    } else {
        STEP_MAINLOOP("L2::evict_first")
    }

    // Batched butterfly reduce: 5 rounds x 8 independent shfls.
#pragma unroll
    for (int off = 16; off > 0; off >>= 1)
#pragma unroll
        for (int r = 0; r < 8; ++r)
            s[r] += __shfl_xor_sync(0xFFFFFFFFu, s[r], off);

    if (lane == 0) {
#pragma unroll
        for (int r = 0; r < 8; ++r) part[r][warp] = s[r];
    }
    __syncthreads();

    if (threadIdx.x < 8) {
        const int j = jbase + threadIdx.x;
        float v = part[threadIdx.x][0] + part[threadIdx.x][1] +
                  part[threadIdx.x][2] + part[threadIdx.x][3] +
                  part[threadIdx.x][4] + part[threadIdx.x][5] +
                  part[threadIdx.x][6] + part[threadIdx.x][7];
        hout[j] = tanhf(v + g_pre[(size_t)t * H + j] + b[j]);
    }
}

// ---------------------------------------------------------------------------
extern "C" void kernel_launch(void* const* d_in, const int* in_sizes, int n_in,
                              void* d_out, int out_size) {
    const float* x   = (const float*)d_in[0];   // (64, 8192)
    const float* wih = (const float*)d_in[1];   // (8192, 8192)
    const float* whh = (const float*)d_in[2];   // (8192, 8192)
    const float* b   = (const float*)d_in[3];   // (8192,)
    float* out = (float*)d_out;                 // 64*8192

    k_convert<<<(H * (size_t)H) / 16 / 256, 256>>>(whh);
    k_phase1<<<H / 64, 256>>>(x, wih);
    k_step0<<<H / 256, 256>>>(out, b);
    for (int t = 1; t < T; ++t)
        k_step<<<H / 8, 256>>>(out + (size_t)(t - 1) * H,
                               out + (size_t)t * H, b, t);
}

// round 16
// speedup vs baseline: 1.6929x; 1.0378x over previous
#include <cuda_runtime.h>
#include <cuda_fp16.h>
#include <cstdint>

#define H 8192
#define T 64
#define NBLK 296          // persistent blocks: 2/SM on 148 SMs (<= capacity on 152 too)
#define SPLIT_ROWS 5632   // W_hh rows tagged evict_last (kept from R13; harmless)

// Scratch (device globals: sanctioned allocation-free workaround).
__device__ __half g_whh[(size_t)H * (size_t)H];   // fp16 W_hh, 128 MiB
__device__ float g_pre[T * H];                    // pre[t][j] = x_t . W_ih^T

// ---- grid barrier state (sense-reversing; self-consistent across launches) ----
__device__ unsigned g_cnt = 0;
__device__ volatile unsigned g_gen = 0;

__device__ __forceinline__ void grid_barrier() {
    __syncthreads();
    if (threadIdx.x == 0) {
        unsigned gen = g_gen;
        __threadfence();
        if (atomicAdd(&g_cnt, 1u) == NBLK - 1u) {
            atomicExch(&g_cnt, 0u);
            __threadfence();
            g_gen = gen + 1u;
        } else {
            while (g_gen == gen) __nanosleep(64);
        }
    }
    __syncthreads();
}

// ---------------------------------------------------------------------------
// tf32 mma helpers
// ---------------------------------------------------------------------------
__device__ __forceinline__ uint32_t f2tf(float f) {
    uint32_t u;
    asm("cvt.rna.tf32.f32 %0, %1;" : "=r"(u) : "f"(f));
    return u;
}
__device__ __forceinline__ void mma_tf32(float* c,
                                         uint32_t a0, uint32_t a1, uint32_t a2, uint32_t a3,
                                         uint32_t b0, uint32_t b1) {
    asm volatile("mma.sync.aligned.m16n8k8.row.col.f32.tf32.tf32.f32 "
                 "{%0,%1,%2,%3}, {%4,%5,%6,%7}, {%8,%9}, {%0,%1,%2,%3};"
                 : "+f"(c[0]), "+f"(c[1]), "+f"(c[2]), "+f"(c[3])
                 : "r"(a0), "r"(a1), "r"(a2), "r"(a3), "r"(b0), "r"(b1));
}

// ---------------------------------------------------------------------------
// K_PREP: fused  (a) phase-1 tf32 GEMM  pre[t][j] = sum_k x[t][k]*W_ih[j][k]
//                (b) W_hh fp32 -> fp16 convert with 256-bit stores.
// Blocks 0..127: GEMM tiles (64t x 64j).  Blocks 128..16511: convert chunks.
// The two workloads overlap on the memory system (their combined traffic
// ~640MB needs ~90us instead of ~125us serialized).
// ---------------------------------------------------------------------------
#define PREP_GEMM_BLOCKS (H / 64)                       // 128
#define PREP_CONV_BLOCKS ((size_t)H * H / 16 / 256)     // 16384

__global__ void __launch_bounds__(256) k_prep(const float* __restrict__ x,
                                              const float* __restrict__ wih,
                                              const float* __restrict__ whh) {
    if (blockIdx.x >= PREP_GEMM_BLOCKS) {
        // ---- convert part ----
        size_t i = (((size_t)blockIdx.x - PREP_GEMM_BLOCKS) * 256u + threadIdx.x) * 16u;
        uint32_t o[8];
#pragma unroll
        for (int q = 0; q < 4; ++q) {
            float4 a = *reinterpret_cast<const float4*>(whh + i + q * 4);
            __half2 lo = __floats2half2_rn(a.x, a.y);
            __half2 hi = __floats2half2_rn(a.z, a.w);
            o[q * 2 + 0] = reinterpret_cast<unsigned int&>(lo);
            o[q * 2 + 1] = reinterpret_cast<unsigned int&>(hi);
        }
        if ((i >> 13) < SPLIT_ROWS) {
            asm volatile("st.global.L2::evict_last.v8.b32 [%0], {%1,%2,%3,%4,%5,%6,%7,%8};"
                         :: "l"(g_whh + i),
                            "r"(o[0]), "r"(o[1]), "r"(o[2]), "r"(o[3]),
                            "r"(o[4]), "r"(o[5]), "r"(o[6]), "r"(o[7]) : "memory");
        } else {
            asm volatile("st.global.L2::evict_first.v8.b32 [%0], {%1,%2,%3,%4,%5,%6,%7,%8};"
                         :: "l"(g_whh + i),
                            "r"(o[0]), "r"(o[1]), "r"(o[2]), "r"(o[3]),
                            "r"(o[4]), "r"(o[5]), "r"(o[6]), "r"(o[7]) : "memory");
        }
        return;
    }

    // ---- phase-1 GEMM part ----
    __shared__ float As[64 * 36];   // [t][k], row pad 36
    __shared__ float Bs[64 * 36];   // [j][k], row pad 36

    const int tid = threadIdx.x;
    const int warp = tid >> 5;
    const int lane = tid & 31;
    const int wm = warp >> 2;
    const int wn = warp & 3;
    const int g = lane >> 2;
    const int tig = lane & 3;
    const int jb = blockIdx.x * 64;

    float acc[2][2][4];
#pragma unroll
    for (int mt = 0; mt < 2; ++mt)
#pragma unroll
        for (int nt = 0; nt < 2; ++nt)
#pragma unroll
            for (int i = 0; i < 4; ++i) acc[mt][nt][i] = 0.f;

    for (int kc = 0; kc < H; kc += 32) {
#pragma unroll
        for (int p = 0; p < 2; ++p) {
            int idx = tid + p * 256;
            int r = idx >> 3;
            int c4 = (idx & 7) * 4;
            float4 v = *reinterpret_cast<const float4*>(x + (size_t)r * H + kc + c4);
            *reinterpret_cast<float4*>(As + r * 36 + c4) = v;
            float4 w = *reinterpret_cast<const float4*>(wih + (size_t)(jb + r) * H + kc + c4);
            *reinterpret_cast<float4*>(Bs + r * 36 + c4) = w;
        }
        __syncthreads();

#pragma unroll
        for (int ks = 0; ks < 4; ++ks) {
            const int k0 = ks * 8;
            uint32_t a[2][4];
#pragma unroll
            for (int mt = 0; mt < 2; ++mt) {
                int mr = wm * 32 + mt * 16;
                a[mt][0] = f2tf(As[(mr + g)     * 36 + k0 + tig]);
                a[mt][1] = f2tf(As[(mr + g + 8) * 36 + k0 + tig]);
                a[mt][2] = f2tf(As[(mr + g)     * 36 + k0 + tig + 4]);
                a[mt][3] = f2tf(As[(mr + g + 8) * 36 + k0 + tig + 4]);
            }
            uint32_t bfr[2][2];
#pragma unroll
            for (int nt = 0; nt < 2; ++nt) {
                int nr = wn * 16 + nt * 8;
                bfr[nt][0] = f2tf(Bs[(nr + g) * 36 + k0 + tig]);
                bfr[nt][1] = f2tf(Bs[(nr + g) * 36 + k0 + tig + 4]);
            }
#pragma unroll
            for (int mt = 0; mt < 2; ++mt)
#pragma unroll
                for (int nt = 0; nt < 2; ++nt)
                    mma_tf32(acc[mt][nt], a[mt][0], a[mt][1], a[mt][2], a[mt][3],
                             bfr[nt][0], bfr[nt][1]);
        }
        __syncthreads();
    }

#pragma unroll
    for (int mt = 0; mt < 2; ++mt) {
        int t0 = wm * 32 + mt * 16 + g;
#pragma unroll
        for (int nt = 0; nt < 2; ++nt) {
            int j0 = jb + wn * 16 + nt * 8 + tig * 2;
            *reinterpret_cast<float2*>(g_pre + (size_t)t0 * H + j0) =
                make_float2(acc[mt][nt][0], acc[mt][nt][1]);
            *reinterpret_cast<float2*>(g_pre + (size_t)(t0 + 8) * H + j0) =
                make_float2(acc[mt][nt][2], acc[mt][nt][3]);
        }
    }
}

// ---------------------------------------------------------------------------
// K_RNN: persistent recurrence.  One launch; 296 blocks (all resident);
// grid barrier between steps.  Per step each block processes 3-4 chunks of
// 8 rows with the R12 inner loop (k-split warps, register h, LDG.256,
// batched shuffle reduce).  Removes 63 launch gaps + per-launch L1 flushes.
// Correctness: every step reads/writes fresh addresses (out + t*H), so no
// L1 staleness; cross-block visibility via the barrier's threadfence.
// ---------------------------------------------------------------------------
#define STEP_MAINLOOP(LDMOD)                                                    \
    _Pragma("unroll")                                                           \
    for (int it = 0; it < 2; ++it) {                                            \
        _Pragma("unroll")                                                       \
        for (int r = 0; r < 8; ++r) {                                           \
            uint32_t w0, w1, w2, w3, w4, w5, w6, w7;                            \
            asm volatile("ld.global.nc." LDMOD ".v8.b32 "                       \
                         "{%0,%1,%2,%3,%4,%5,%6,%7}, [%8];"                     \
                         : "=r"(w0), "=r"(w1), "=r"(w2), "=r"(w3),              \
                           "=r"(w4), "=r"(w5), "=r"(w6), "=r"(w7)               \
                         : "l"(wbase + (size_t)r * H + it * 512));              \
            float2 f0 = __half22float2(reinterpret_cast<__half2&>(w0));         \
            float2 f1 = __half22float2(reinterpret_cast<__half2&>(w1));         \
            float2 f2 = __half22float2(reinterpret_cast<__half2&>(w2));         \
            float2 f3 = __half22float2(reinterpret_cast<__half2&>(w3));         \
            float2 f4 = __half22float2(reinterpret_cast<__half2&>(w4));         \
            float2 f5 = __half22float2(reinterpret_cast<__half2&>(w5));         \
            float2 f6 = __half22float2(reinterpret_cast<__half2&>(w6));         \
            float2 f7 = __half22float2(reinterpret_cast<__half2&>(w7));         \
            float acc = s[r];                                                   \
            acc = fmaf(f0.x, hr[it][0],  acc);                                  \
            acc = fmaf(f0.y, hr[it][1],  acc);                                  \
            acc = fmaf(f1.x, hr[it][2],  acc);                                  \
            acc = fmaf(f1.y, hr[it][3],  acc);                                  \
            acc = fmaf(f2.x, hr[it][4],  acc);                                  \
            acc = fmaf(f2.y, hr[it][5],  acc);                                  \
            acc = fmaf(f3.x, hr[it][6],  acc);                                  \
            acc = fmaf(f3.y, hr[it][7],  acc);                                  \
            acc = fmaf(f4.x, hr[it][8],  acc);                                  \
            acc = fmaf(f4.y, hr[it][9],  acc);                                  \
            acc = fmaf(f5.x, hr[it][10], acc);                                  \
            acc = fmaf(f5.y, hr[it][11], acc);                                  \
            acc = fmaf(f6.x, hr[it][12], acc);                                  \
            acc = fmaf(f6.y, hr[it][13], acc);                                  \
            acc = fmaf(f7.x, hr[it][14], acc);                                  \
            acc = fmaf(f7.y, hr[it][15], acc);                                  \
            s[r] = acc;                                                         \
        }                                                                       \
    }

__global__ void __launch_bounds__(256, 2) k_rnn(float* __restrict__ out,
                                                const float* __restrict__ b) {
    __shared__ float part[8][8];   // [row][warp]
    const int warp = threadIdx.x >> 5;
    const int lane = threadIdx.x & 31;
    const int k0 = warp * 1024 + lane * 16;

    // ---- step 0: h0 = tanh(pre0 + b) ----
    for (int j = blockIdx.x * 256 + threadIdx.x; j < H; j += NBLK * 256)
        out[j] = tanhf(g_pre[j] + b[j]);
    grid_barrier();

    for (int t = 1; t < T; ++t) {
        const float* hprev = out + (size_t)(t - 1) * H;
        float* hout = out + (size_t)t * H;

        // Preload this lane's h slice once per step: h[k0 + it*512 + 0..15]
        float hr[2][16];
#pragma unroll
        for (int it = 0; it < 2; ++it)
#pragma unroll
            for (int q = 0; q < 4; ++q) {
                float4 a = *reinterpret_cast<const float4*>(hprev + k0 + it * 512 + q * 4);
                hr[it][q * 4 + 0] = a.x;
                hr[it][q * 4 + 1] = a.y;
                hr[it][q * 4 + 2] = a.z;
                hr[it][q * 4 + 3] = a.w;
            }

        for (int chunk = blockIdx.x; chunk < H / 8; chunk += NBLK) {
            const int jbase = chunk * 8;
            const __half* wbase = g_whh + (size_t)jbase * H + k0;

            float s[8];
#pragma unroll
            for (int r = 0; r < 8; ++r) s[r] = 0.f;

            if (jbase < SPLIT_ROWS) {
                STEP_MAINLOOP("L2::evict_last")
            } else {
                STEP_MAINLOOP("L2::evict_first")
            }

            // Batched butterfly reduce: 5 rounds x 8 independent shfls.
#pragma unroll
            for (int off = 16; off > 0; off >>= 1)
#pragma unroll
                for (int r = 0; r < 8; ++r)
                    s[r] += __shfl_xor_sync(0xFFFFFFFFu, s[r], off);

            if (lane == 0) {
#pragma unroll
                for (int r = 0; r < 8; ++r) part[r][warp] = s[r];
            }
            __syncthreads();

            if (threadIdx.x < 8) {
                const int j = jbase + threadIdx.x;
                float v = part[threadIdx.x][0] + part[threadIdx.x][1] +
                          part[threadIdx.x][2] + part[threadIdx.x][3] +
                          part[threadIdx.x][4] + part[threadIdx.x][5] +
                          part[threadIdx.x][6] + part[threadIdx.x][7];
                hout[j] = tanhf(v + g_pre[(size_t)t * H + j] + b[j]);
            }
            __syncthreads();   // protect part[] before next chunk
        }
        grid_barrier();
    }
}

// ---------------------------------------------------------------------------
extern "C" void kernel_launch(void* const* d_in, const int* in_sizes, int n_in,
                              void* d_out, int out_size) {
    const float* x   = (const float*)d_in[0];   // (64, 8192)
    const float* wih = (const float*)d_in[1];   // (8192, 8192)
    const float* whh = (const float*)d_in[2];   // (8192, 8192)
    const float* b   = (const float*)d_in[3];   // (8192,)
    float* out = (float*)d_out;                 // 64*8192

    k_prep<<<(unsigned)(PREP_GEMM_BLOCKS + PREP_CONV_BLOCKS), 256>>>(x, wih, whh);
    k_rnn<<<NBLK, 256>>>(out, b);
}